// round 1
// baseline (speedup 1.0000x reference)
#include <cuda_runtime.h>
#include <cstddef>

#define B_  8
#define N_  128
#define FN_ 64

// Precomputed node projections: P[b][n][part][l]
// part 0 = H@Wi_att, 1 = H@Wj_att, 2 = H@Wi_nei, 3 = H@Wj_nei
__device__ float g_P[B_ * N_ * 4 * FN_];

// ---- f32x2 packed-FMA helpers (Blackwell FFMA2, only reachable via PTX) ----
__device__ __forceinline__ double pack2d(float x, float y) {
    double r;
    asm("mov.b64 %0, {%1, %2};" : "=d"(r) : "f"(x), "f"(y));
    return r;
}
__device__ __forceinline__ void fma2(double& acc, double a, double b) {
    asm("fma.rn.f32x2 %0, %1, %2, %0;" : "+d"(acc) : "d"(a), "d"(b));
}
__device__ __forceinline__ float2 unpack2d(double v) {
    float2 f;
    asm("mov.b64 {%0, %1}, %2;" : "=f"(f.x), "=f"(f.y) : "d"(v));
    return f;
}

// ---------------------------------------------------------------------------
// Kernel 1: per-node projections H @ {Wi_att, Wj_att, Wi_nei, Wj_nei}
// grid = B*N blocks, 256 threads: part = t>>6, l = t&63
// ---------------------------------------------------------------------------
__global__ void __launch_bounds__(256)
precompute_kernel(const float* __restrict__ H,
                  const float* __restrict__ Watt,
                  const float* __restrict__ Wnei) {
    const int bn = blockIdx.x;                  // b*N + n
    __shared__ float h[FN_];
    const int t = threadIdx.x;
    if (t < FN_) h[t] = H[bn * FN_ + t];
    __syncthreads();

    const int part = t >> 6;
    const int l    = t & 63;
    const float* __restrict__ W = (part < 2) ? Watt : Wnei;
    const int rowoff = (part & 1) * FN_;        // Wi rows [0,64), Wj rows [64,128)

    float acc = 0.f;
    #pragma unroll 8
    for (int f = 0; f < FN_; f++)
        acc = fmaf(h[f], W[(rowoff + f) * FN_ + l], acc);

    g_P[(bn * 4 + part) * FN_ + l] = acc;
}

// ---------------------------------------------------------------------------
// Kernel 2: main fused pair loop.
// Block = 128 threads covering TWO j columns (t>>6 selects j within pair).
// Thread owns (b, j, l); computes BOTH branches -> no barriers / shared / atomics.
// grid = B * N/2 = 512 blocks.
// ---------------------------------------------------------------------------
__global__ void __launch_bounds__(128)
main_kernel(const float* __restrict__ A,
            const float* __restrict__ E,
            const float* __restrict__ Watt,
            const float* __restrict__ Wnei,
            const float* __restrict__ biasAtt,
            const float* __restrict__ biasNei,
            float* __restrict__ out) {
    const int t = threadIdx.x;
    const int l = t & 63;
    const int b = blockIdx.x >> 6;                       // 64 j-pairs per b
    const int j = ((blockIdx.x & 63) << 1) + (t >> 6);

    // Edge-weight columns We_att[:,l], We_nei[:,l] (W rows 128..191), packed f32x2 over e.
    double wA[FN_ / 2], wN[FN_ / 2];
    #pragma unroll
    for (int m = 0; m < FN_ / 2; m++) {
        wA[m] = pack2d(Watt[(128 + 2 * m) * FN_ + l], Watt[(128 + 2 * m + 1) * FN_ + l]);
        wN[m] = pack2d(Wnei[(128 + 2 * m) * FN_ + l], Wnei[(128 + 2 * m + 1) * FN_ + l]);
    }

    const float hjA = g_P[(((b * N_) + j) * 4 + 1) * FN_ + l];
    const float hjN = g_P[(((b * N_) + j) * 4 + 3) * FN_ + l];
    const float bsA = biasAtt[l];
    const float bsN = biasNei[l];

    const float* __restrict__ Acol = A + (size_t)b * N_ * N_ + j;   // stride N_ over i
    const size_t e_base   = (((size_t)b * N_) * N_ + j) * FN_;      // E[b,0,j,0]
    const size_t e_stride = (size_t)N_ * FN_ / 2;                   // per-i stride, double2 units
    const float* __restrict__ Pb = g_P + (size_t)b * N_ * 4 * FN_;

    float acc = 0.f;
    for (int i = 0; i < N_; i++) {
        const float a   = Acol[(size_t)i * N_];
        const float hiA = Pb[(i * 4 + 0) * FN_ + l];
        const float hiN = Pb[(i * 4 + 2) * FN_ + l];

        const double2* __restrict__ Er =
            (const double2*)(E + e_base) + (size_t)i * (e_stride / 2);

        double aA0 = 0.0, aA1 = 0.0, aN0 = 0.0, aN1 = 0.0;
        #pragma unroll
        for (int k = 0; k < 16; k++) {
            const double2 e = Er[k];              // bitwise (f32,f32) pairs: E[4k..4k+3]
            fma2(aA0, e.x, wA[2 * k]);
            fma2(aA1, e.y, wA[2 * k + 1]);
            fma2(aN0, e.x, wN[2 * k]);
            fma2(aN1, e.y, wN[2 * k + 1]);
        }
        const float2 fA0 = unpack2d(aA0), fA1 = unpack2d(aA1);
        const float2 fN0 = unpack2d(aN0), fN1 = unpack2d(aN1);
        const float dA = (fA0.x + fA0.y) + (fA1.x + fA1.y);
        const float dN = (fN0.x + fN0.y) + (fN1.x + fN1.y);

        const float att  = fmaf(a, dA + hiA + hjA, bsA);
        const float conv = fmaf(a, dN + hiN + hjN, bsN);

        if (conv > 0.f)                            // relu gate
            acc += __fdividef(conv, 1.f + __expf(-att));   // * sigmoid(att)
    }

    out[(((size_t)b * N_) + j) * FN_ + l] = acc;
}

// ---------------------------------------------------------------------------
extern "C" void kernel_launch(void* const* d_in, const int* in_sizes, int n_in,
                              void* d_out, int out_size) {
    const float* H    = (const float*)d_in[0];
    const float* A    = (const float*)d_in[1];
    const float* E    = (const float*)d_in[2];
    const float* Watt = (const float*)d_in[3];
    const float* Wnei = (const float*)d_in[4];
    const float* bAtt = (const float*)d_in[5];
    const float* bNei = (const float*)d_in[6];
    float* out = (float*)d_out;

    precompute_kernel<<<B_ * N_, 256>>>(H, Watt, Wnei);
    main_kernel<<<B_ * N_ / 2, 128>>>(A, E, Watt, Wnei, bAtt, bNei, out);
}

// round 3
// speedup vs baseline: 2.7461x; 2.7461x over previous
#include <cuda_runtime.h>
#include <cstdint>
#include <cstddef>

#define Bv     8
#define Nv     128
#define FNv    64
#define IPC    8
#define CHUNKS 16

// ------------------------------ device scratch ------------------------------
__device__ double g_Wpair[FNv * FNv];            // [k][l] = (We_att[k][l], We_nei[k][l])
__device__ double g_PiPair[Bv * Nv * FNv];       // [b][n][l] = (H@Wi_att, H@Wi_nei)
__device__ double g_PjPair[Bv * Nv * FNv];       // [b][n][l] = (H@Wj_att, H@Wj_nei)
__device__ float  g_part[Bv * CHUNKS * Nv * FNv];

// ------------------------------ helpers ------------------------------
__device__ __forceinline__ double pack2d(float x, float y) {
    double r; asm("mov.b64 %0, {%1, %2};" : "=d"(r) : "f"(x), "f"(y)); return r;
}
__device__ __forceinline__ void fma2(double& acc, double a, double b) {
    asm("fma.rn.f32x2 %0, %1, %2, %0;" : "+d"(acc) : "d"(a), "d"(b));
}
__device__ __forceinline__ double add2(double a, double b) {
    double r; asm("add.rn.f32x2 %0, %1, %2;" : "=d"(r) : "d"(a), "d"(b)); return r;
}
__device__ __forceinline__ float2 unpack2d(double v) {
    float2 f; asm("mov.b64 {%0, %1}, %2;" : "=f"(f.x), "=f"(f.y) : "d"(v)); return f;
}
__device__ __forceinline__ uint32_t smem_u32(const void* p) {
    uint32_t a;
    asm("{ .reg .u64 t; cvta.to.shared.u64 t, %1; cvt.u32.u64 %0, t; }" : "=r"(a) : "l"(p));
    return a;
}
__device__ __forceinline__ void cp16(uint32_t dst, const void* src) {
    asm volatile("cp.async.cg.shared.global [%0], [%1], 16;" :: "r"(dst), "l"(src) : "memory");
}
__device__ __forceinline__ void cp_commit() {
    asm volatile("cp.async.commit_group;" ::: "memory");
}
template <int N>
__device__ __forceinline__ void cp_wait() {
    asm volatile("cp.async.wait_group %0;" :: "n"(N) : "memory");
}

// ------------------------------ prep kernel ------------------------------
// blocks [0,1024): node projection pairs. blocks [1024,1032): edge-weight pairs.
__global__ void __launch_bounds__(128)
prep_kernel(const float* __restrict__ H,
            const float* __restrict__ Watt,
            const float* __restrict__ Wnei) {
    const int t = threadIdx.x;
    if (blockIdx.x < Bv * Nv) {
        const int bn = blockIdx.x;
        __shared__ float h[FNv];
        if (t < FNv) h[t] = H[bn * FNv + t];
        __syncthreads();

        const int l   = t & 63;
        const int sel = t >> 6;                 // 0 -> Pi (rows 0..63), 1 -> Pj (rows 64..127)
        const int ro  = sel * FNv;
        float va = 0.f, vn = 0.f;
        #pragma unroll 8
        for (int f = 0; f < FNv; f++) {
            const float hf = h[f];
            va = fmaf(hf, Watt[(ro + f) * FNv + l], va);
            vn = fmaf(hf, Wnei[(ro + f) * FNv + l], vn);
        }
        const double pr = pack2d(va, vn);
        if (sel == 0) g_PiPair[bn * FNv + l] = pr;
        else          g_PjPair[bn * FNv + l] = pr;
    } else {
        const int base = (blockIdx.x - Bv * Nv) * 512;
        #pragma unroll
        for (int v = 0; v < 4; v++) {
            const int id = base + v * 128 + t;   // 0..4095
            const int k = id >> 6, l = id & 63;
            g_Wpair[id] = pack2d(Watt[(2 * FNv + k) * FNv + l],
                                 Wnei[(2 * FNv + k) * FNv + l]);
        }
    }
}

// ------------------------------ main kernel ------------------------------
// 128 CTAs: (b, chunk of 8 i's). 256 threads: tl = t>>4 (l-group), tj = t&15.
// Thread owns j = tj + 16r (r=0..7), l = tl*4 + cc (cc=0..3).
#define OFF_W   0            // Wd[k][c] doubles        : 32768 B
#define OFF_E   32768        // Ed[j][k] doubles, row 66: 67584 B
#define ED_ROW  66
#define OFF_RAW 100352       // raw[2][128][272B]       : 69632 B
#define RAW_BUF 34816
#define RAW_ROW 272
#define OFF_PI  169984       // Pi pairs [64] doubles   : 512 B
#define SMEM_DYN 170496

__global__ void __launch_bounds__(256, 1)
main_kernel(const float* __restrict__ A,
            const float* __restrict__ E,
            const float* __restrict__ biasA,
            const float* __restrict__ biasN) {
    extern __shared__ char sm[];
    double* __restrict__ Wd  = (double*)(sm + OFF_W);
    double* __restrict__ Ed  = (double*)(sm + OFF_E);
    double* __restrict__ Pis = (double*)(sm + OFF_PI);
    const uint32_t sb = smem_u32(sm);

    const int t  = threadIdx.x;
    const int tl = t >> 4;
    const int tj = t & 15;
    const int b     = blockIdx.x >> 4;
    const int i0    = (blockIdx.x & 15) * IPC;

    // ---- load combined weights into smem (4096 doubles) ----
    {
        const float4* wg = (const float4*)g_Wpair;
        float4* ws = (float4*)Wd;
        #pragma unroll
        for (int v = 0; v < 8; v++) ws[v * 256 + t] = wg[v * 256 + t];
    }

    // ---- bias registers ----
    float brA[4], brN[4];
    #pragma unroll
    for (int cc = 0; cc < 4; cc++) {
        brA[cc] = biasA[tl * 4 + cc];
        brN[cc] = biasN[tl * 4 + cc];
    }

    // ---- prefetch first E tile ----
    const char* Ebase = (const char*)(E + ((size_t)(b * Nv + i0)) * Nv * FNv);
    {
        #pragma unroll
        for (int v = 0; v < 8; v++) {
            const int n = v * 256 + t;                 // 16B chunk id
            const int row = n >> 4, cc = n & 15;
            cp16(sb + OFF_RAW + row * RAW_ROW + cc * 16, Ebase + n * 16);
        }
        cp_commit();
    }

    float outacc[8][4];
    #pragma unroll
    for (int r = 0; r < 8; r++)
        #pragma unroll
        for (int c = 0; c < 4; c++) outacc[r][c] = 0.f;

    for (int ii = 0; ii < IPC; ii++) {
        // prefetch next tile
        if (ii + 1 < IPC) {
            const char* Enext = (const char*)(E + ((size_t)(b * Nv + i0 + ii + 1)) * Nv * FNv);
            const uint32_t rb = sb + OFF_RAW + ((ii + 1) & 1) * RAW_BUF;
            #pragma unroll
            for (int v = 0; v < 8; v++) {
                const int n = v * 256 + t;
                const int row = n >> 4, cc = n & 15;
                cp16(rb + row * RAW_ROW + cc * 16, Enext + n * 16);
            }
            cp_commit();
            cp_wait<1>();
        } else {
            cp_wait<0>();
        }
        __syncthreads();   // raw[ii&1] ready; previous GEMM's Ed reads finished

        // ---- spread raw floats -> dup-doubles in Ed ----
        {
            const int j = t & 127, half = t >> 7;
            const float4* rs = (const float4*)(sm + OFF_RAW + (ii & 1) * RAW_BUF
                                               + j * RAW_ROW + half * 128);
            double2* dp = (double2*)(Ed + j * ED_ROW + half * 32);
            #pragma unroll
            for (int m = 0; m < 8; m++) {
                const float4 v = rs[m];
                double2 d0, d1;
                d0.x = pack2d(v.x, v.x); d0.y = pack2d(v.y, v.y);
                d1.x = pack2d(v.z, v.z); d1.y = pack2d(v.w, v.w);
                dp[2 * m]     = d0;
                dp[2 * m + 1] = d1;
            }
        }
        if (t < 64) Pis[t] = g_PiPair[(size_t)(b * Nv + i0 + ii) * FNv + t];
        __syncthreads();

        // ---- GEMM: acc[r][c] = sum_k Ed[tj+16r][k] (*pair) Wd[k][tl*4+c] ----
        double acc[8][4];
        #pragma unroll
        for (int r = 0; r < 8; r++)
            #pragma unroll
            for (int c = 0; c < 4; c++) acc[r][c] = 0.0;

        const double* __restrict__ ep = Ed + tj * ED_ROW;
        const double* __restrict__ wp = Wd + tl * 4;

        #pragma unroll 4
        for (int k2 = 0; k2 < 32; k2++) {
            const int k = 2 * k2;
            double2 e2[8];
            #pragma unroll
            for (int r = 0; r < 8; r++)
                e2[r] = *(const double2*)(ep + r * (16 * ED_ROW) + k);
            const double2 wlo0 = *(const double2*)(wp + (size_t)k * 64);
            const double2 whi0 = *(const double2*)(wp + (size_t)k * 64 + 2);
            const double2 wlo1 = *(const double2*)(wp + (size_t)(k + 1) * 64);
            const double2 whi1 = *(const double2*)(wp + (size_t)(k + 1) * 64 + 2);
            #pragma unroll
            for (int r = 0; r < 8; r++) {
                fma2(acc[r][0], e2[r].x, wlo0.x);
                fma2(acc[r][1], e2[r].x, wlo0.y);
                fma2(acc[r][2], e2[r].x, whi0.x);
                fma2(acc[r][3], e2[r].x, whi0.y);
                fma2(acc[r][0], e2[r].y, wlo1.x);
                fma2(acc[r][1], e2[r].y, wlo1.y);
                fma2(acc[r][2], e2[r].y, whi1.x);
                fma2(acc[r][3], e2[r].y, whi1.y);
            }
        }

        // ---- epilogue: gate + accumulate over i ----
        const float* __restrict__ arow = A + ((size_t)(b * Nv + i0 + ii)) * Nv;
        double piv[4];
        #pragma unroll
        for (int cc = 0; cc < 4; cc++) piv[cc] = Pis[tl * 4 + cc];
        const double* __restrict__ pjb = g_PjPair + (size_t)(b * Nv) * FNv + tl * 4;

        #pragma unroll
        for (int r = 0; r < 8; r++) {
            const int j = tj + 16 * r;
            const float a_ij = __ldg(arow + j);
            const double2 pj0 = __ldg((const double2*)(pjb + (size_t)j * FNv));
            const double2 pj1 = __ldg((const double2*)(pjb + (size_t)j * FNv + 2));
            #pragma unroll
            for (int cc = 0; cc < 4; cc++) {
                const double pjv = (cc == 0) ? pj0.x : (cc == 1) ? pj0.y
                                 : (cc == 2) ? pj1.x : pj1.y;
                const double s = add2(add2(acc[r][cc], piv[cc]), pjv);
                const float2 f = unpack2d(s);
                const float att = fmaf(a_ij, f.x, brA[cc]);
                const float cv  = fmaf(a_ij, f.y, brN[cc]);
                float th;
                asm("tanh.approx.f32 %0, %1;" : "=f"(th) : "f"(att * 0.5f));
                const float sg = fmaf(0.5f, th, 0.5f);
                outacc[r][cc] = fmaf(fmaxf(cv, 0.f), sg, outacc[r][cc]);
            }
        }
    }

    // ---- store partials: g_part[cta][j][l] ----
    float* __restrict__ dst = g_part + ((size_t)blockIdx.x * Nv) * FNv;
    #pragma unroll
    for (int r = 0; r < 8; r++) {
        const int j = tj + 16 * r;
        float4 v = make_float4(outacc[r][0], outacc[r][1], outacc[r][2], outacc[r][3]);
        *(float4*)(dst + (size_t)j * FNv + tl * 4) = v;
    }
}

// ------------------------------ reduce kernel ------------------------------
__global__ void __launch_bounds__(256)
reduce_kernel(float* __restrict__ out) {
    const int f4 = blockIdx.x * 256 + threadIdx.x;   // 0..16383 float4 groups
    const int b = f4 >> 11;
    const int r = f4 & 2047;
    const float4* P = (const float4*)g_part;
    float4 s = make_float4(0.f, 0.f, 0.f, 0.f);
    #pragma unroll
    for (int c = 0; c < CHUNKS; c++) {
        const float4 v = P[((size_t)(b * CHUNKS + c)) * 2048 + r];
        s.x += v.x; s.y += v.y; s.z += v.z; s.w += v.w;
    }
    ((float4*)out)[b * 2048 + r] = s;
}

// ------------------------------ launch ------------------------------
extern "C" void kernel_launch(void* const* d_in, const int* in_sizes, int n_in,
                              void* d_out, int out_size) {
    const float* H    = (const float*)d_in[0];
    const float* A    = (const float*)d_in[1];
    const float* E    = (const float*)d_in[2];
    const float* Watt = (const float*)d_in[3];
    const float* Wnei = (const float*)d_in[4];
    const float* bAtt = (const float*)d_in[5];
    const float* bNei = (const float*)d_in[6];
    float* out = (float*)d_out;

    cudaFuncSetAttribute(main_kernel, cudaFuncAttributeMaxDynamicSharedMemorySize, SMEM_DYN);

    prep_kernel<<<Bv * Nv + 8, 128>>>(H, Watt, Wnei);
    main_kernel<<<Bv * CHUNKS, 256, SMEM_DYN>>>(A, E, bAtt, bNei);
    reduce_kernel<<<64, 256>>>(out);
}

// round 4
// speedup vs baseline: 6.1677x; 2.2460x over previous
#include <cuda_runtime.h>
#include <cstdint>
#include <cstddef>

#define Bv     8
#define Nv     128
#define FNv    64
#define IPC    8
#define CHUNKS 16

// ------------------------------ device scratch ------------------------------
__device__ float  g_Wt[128 * 68];        // B operand [n=2l+br][k(64)+pad4], tf32 bits
__device__ float2 g_Pi[Bv * Nv * FNv];   // (att,nei) node proj, Wi part
__device__ float2 g_Pj[Bv * Nv * FNv];   // (att,nei) node proj, Wj part
__device__ float  g_part[Bv * CHUNKS * Nv * FNv];

// ------------------------------ helpers ------------------------------
__device__ __forceinline__ uint32_t cvt_tf32(float x) {
    uint32_t r; asm("cvt.rna.tf32.f32 %0, %1;" : "=r"(r) : "f"(x)); return r;
}
__device__ __forceinline__ uint32_t smem_u32(const void* p) {
    uint32_t a;
    asm("{ .reg .u64 t; cvta.to.shared.u64 t, %1; cvt.u32.u64 %0, t; }" : "=r"(a) : "l"(p));
    return a;
}
__device__ __forceinline__ void cp16(uint32_t dst, const void* src) {
    asm volatile("cp.async.cg.shared.global [%0], [%1], 16;" :: "r"(dst), "l"(src) : "memory");
}
__device__ __forceinline__ void cp_commit() {
    asm volatile("cp.async.commit_group;" ::: "memory");
}
template <int N>
__device__ __forceinline__ void cp_wait() {
    asm volatile("cp.async.wait_group %0;" :: "n"(N) : "memory");
}
__device__ __forceinline__ void mma8(float* c, const uint32_t* a, const uint32_t* b) {
    asm volatile(
        "mma.sync.aligned.m16n8k8.row.col.f32.tf32.tf32.f32 "
        "{%0,%1,%2,%3}, {%4,%5,%6,%7}, {%8,%9}, {%0,%1,%2,%3};"
        : "+f"(c[0]), "+f"(c[1]), "+f"(c[2]), "+f"(c[3])
        : "r"(a[0]), "r"(a[1]), "r"(a[2]), "r"(a[3]), "r"(b[0]), "r"(b[1]));
}

// ------------------------------ prep kernel ------------------------------
// blocks 0..127: node projections (8 nodes each). blocks 128..135: g_Wt fill.
__global__ void __launch_bounds__(256)
prep_kernel(const float* __restrict__ H,
            const float* __restrict__ Watt,
            const float* __restrict__ Wnei) {
    const int t = threadIdx.x;
    if (blockIdx.x < 128) {
        __shared__ float Hs[8][64];
        const int bn0 = blockIdx.x * 8;
        #pragma unroll
        for (int v = 0; v < 2; v++) {
            const int idx = v * 256 + t;
            Hs[idx >> 6][idx & 63] = H[bn0 * 64 + idx];
        }
        __syncthreads();

        const int l = t & 63, half = (t >> 6) & 1, part = t >> 7;
        const float* __restrict__ WaP = Watt + (part * 64) * 64 + l;
        const float* __restrict__ WnP = Wnei + (part * 64) * 64 + l;
        float va[4] = {0.f, 0.f, 0.f, 0.f};
        float vn[4] = {0.f, 0.f, 0.f, 0.f};
        #pragma unroll 8
        for (int f = 0; f < 64; f++) {
            const float wa = __ldg(WaP + f * 64);
            const float wq = __ldg(WnP + f * 64);
            #pragma unroll
            for (int nn = 0; nn < 4; nn++) {
                const float h = Hs[half * 4 + nn][f];
                va[nn] = fmaf(h, wa, va[nn]);
                vn[nn] = fmaf(h, wq, vn[nn]);
            }
        }
        float2* __restrict__ dstp = (part == 0) ? g_Pi : g_Pj;
        #pragma unroll
        for (int nn = 0; nn < 4; nn++)
            dstp[(bn0 + half * 4 + nn) * 64 + l] = make_float2(va[nn], vn[nn]);
    } else {
        const int base = (blockIdx.x - 128) * 1088;
        #pragma unroll
        for (int v = 0; v < 5; v++) {
            const int r = v * 256 + t;
            if (r < 1088) {
                const int idx = base + r;            // < 8704 = 128*68
                const int n = idx / 68, k = idx % 68;
                const int l = n >> 1, br = n & 1;
                float val = 0.f;
                if (k < 64) {
                    const float* W = br ? Wnei : Watt;
                    val = W[(128 + k) * 64 + l];
                }
                g_Wt[idx] = __uint_as_float(cvt_tf32(val));
            }
        }
    }
}

// ------------------------------ main kernel ------------------------------
#define EROW   68
#define EBUF   (128 * EROW * 4)       // 34816
#define PJROW  68                      // float2 units (544 B rows)
#define OFF_W  0
#define OFF_E  34816
#define OFF_PJ 104448
#define OFF_PI 174080
#define OFF_A  178176
#define SMEM_DYN (182272 + 1024)

__global__ void __launch_bounds__(256, 1)
main_kernel(const float* __restrict__ A,
            const float* __restrict__ E,
            const float* __restrict__ biasA,
            const float* __restrict__ biasN) {
    extern __shared__ char smraw[];
    char* sm = (char*)(((uintptr_t)smraw + 1023) & ~(uintptr_t)1023);
    const uint32_t sb = smem_u32(sm);

    const int t = threadIdx.x, lane = t & 31, wid = t >> 5;
    const int g = lane >> 2, tg = lane & 3;
    const int b = blockIdx.x >> 4, chunk = blockIdx.x & 15, i0 = chunk * IPC;
    const int mbase = (wid & 3) * 32;          // j-range of this warp
    const int wn    = wid >> 2;
    const int lbase = wn * 32;                 // l-range
    const int nrow0 = wn * 64;                 // Wt row base

    // ---- group 0: statics + E tile 0 ----
    {
        #pragma unroll
        for (int v = 0; v < 9; v++) {
            const int n = v * 256 + t;
            if (n < 2176) cp16(sb + OFF_W + n * 16, (const char*)g_Wt + n * 16);
        }
        const char* Eg = (const char*)(E + ((size_t)(b * Nv + i0)) * Nv * FNv);
        #pragma unroll
        for (int v = 0; v < 8; v++) {
            const int n = v * 256 + t, row = n >> 4, c = n & 15;
            cp16(sb + OFF_E + row * 272 + c * 16, Eg + n * 16);
        }
        const char* Pg = (const char*)(g_Pj + (size_t)b * Nv * FNv);
        #pragma unroll
        for (int v = 0; v < 16; v++) {
            const int n = v * 256 + t, row = n >> 5, c = n & 31;
            cp16(sb + OFF_PJ + row * 544 + c * 16, Pg + n * 16);
        }
        cp16(sb + OFF_PI + t * 16, (const char*)(g_Pi + (size_t)(b * Nv + i0) * FNv) + t * 16);
        cp16(sb + OFF_A + t * 16, (const char*)(A + (size_t)(b * Nv + i0) * Nv) + t * 16);
        cp_commit();
    }

    float brA[8], brN[8];
    #pragma unroll
    for (int nt = 0; nt < 8; nt++) {
        brA[nt] = __ldg(biasA + lbase + nt * 4 + tg);
        brN[nt] = __ldg(biasN + lbase + nt * 4 + tg);
    }

    float outacc[2][2][8];
    #pragma unroll
    for (int mt = 0; mt < 2; mt++)
        #pragma unroll
        for (int h = 0; h < 2; h++)
            #pragma unroll
            for (int nt = 0; nt < 8; nt++) outacc[mt][h][nt] = 0.f;

    for (int ii = 0; ii < IPC; ii++) {
        if (ii + 1 < IPC) {
            const char* Eg = (const char*)(E + ((size_t)(b * Nv + i0 + ii + 1)) * Nv * FNv);
            const uint32_t dstb = sb + OFF_E + ((ii + 1) & 1) * EBUF;
            #pragma unroll
            for (int v = 0; v < 8; v++) {
                const int n = v * 256 + t, row = n >> 4, c = n & 15;
                cp16(dstb + row * 272 + c * 16, Eg + n * 16);
            }
            cp_commit();
            cp_wait<1>();
        } else {
            cp_wait<0>();
        }
        __syncthreads();           // (a) current E tile + statics visible

        const float* __restrict__ Eb = (const float*)(sm + OFF_E + (ii & 1) * EBUF);
        const uint32_t* __restrict__ Wb = (const uint32_t*)(sm + OFF_W);

        float c[2][8][4];
        #pragma unroll
        for (int mt = 0; mt < 2; mt++)
            #pragma unroll
            for (int nt = 0; nt < 8; nt++)
                #pragma unroll
                for (int q = 0; q < 4; q++) c[mt][nt][q] = 0.f;

        #pragma unroll
        for (int ks = 0; ks < 8; ks++) {
            const int k0 = ks * 8;
            uint32_t a[2][4];
            #pragma unroll
            for (int mt = 0; mt < 2; mt++) {
                const float* ap = Eb + (mbase + mt * 16 + g) * EROW + k0 + tg;
                a[mt][0] = cvt_tf32(ap[0]);
                a[mt][1] = cvt_tf32(ap[8 * EROW]);
                a[mt][2] = cvt_tf32(ap[4]);
                a[mt][3] = cvt_tf32(ap[8 * EROW + 4]);
            }
            uint32_t bf[8][2];
            #pragma unroll
            for (int nt = 0; nt < 8; nt++) {
                const uint32_t* bp = Wb + (nrow0 + nt * 8 + g) * EROW + k0 + tg;
                bf[nt][0] = bp[0];
                bf[nt][1] = bp[4];
            }
            #pragma unroll
            for (int mt = 0; mt < 2; mt++)
                #pragma unroll
                for (int nt = 0; nt < 8; nt++)
                    mma8(c[mt][nt], a[mt], bf[nt]);
        }
        __syncthreads();           // (b) all E reads done -> next cp may overwrite

        // ---- epilogue ----
        const float*  __restrict__ As_i = (const float*)(sm + OFF_A) + ii * 128;
        const float2* __restrict__ Pi_i = (const float2*)(sm + OFF_PI) + ii * 64;
        const float2* __restrict__ Pjs  = (const float2*)(sm + OFF_PJ);

        #pragma unroll
        for (int mt = 0; mt < 2; mt++) {
            const int j0 = mbase + mt * 16 + g;
            const float a0 = As_i[j0], a1 = As_i[j0 + 8];
            const float2* pr0 = Pjs + (size_t)j0 * PJROW;
            const float2* pr1 = pr0 + 8 * PJROW;
            #pragma unroll
            for (int nt = 0; nt < 8; nt++) {
                const int l = lbase + nt * 4 + tg;
                const float2 pi = Pi_i[l];
                const float2 q0 = pr0[l];
                const float2 q1 = pr1[l];
                {
                    const float att = fmaf(a0, c[mt][nt][0] + pi.x + q0.x, brA[nt]);
                    const float cv  = fmaf(a0, c[mt][nt][1] + pi.y + q0.y, brN[nt]);
                    float th; asm("tanh.approx.f32 %0, %1;" : "=f"(th) : "f"(att * 0.5f));
                    outacc[mt][0][nt] = fmaf(fmaxf(cv, 0.f), fmaf(0.5f, th, 0.5f),
                                             outacc[mt][0][nt]);
                }
                {
                    const float att = fmaf(a1, c[mt][nt][2] + pi.x + q1.x, brA[nt]);
                    const float cv  = fmaf(a1, c[mt][nt][3] + pi.y + q1.y, brN[nt]);
                    float th; asm("tanh.approx.f32 %0, %1;" : "=f"(th) : "f"(att * 0.5f));
                    outacc[mt][1][nt] = fmaf(fmaxf(cv, 0.f), fmaf(0.5f, th, 0.5f),
                                             outacc[mt][1][nt]);
                }
            }
        }
    }

    // ---- store partials ----
    float* __restrict__ dst = g_part + (size_t)blockIdx.x * Nv * FNv;
    #pragma unroll
    for (int mt = 0; mt < 2; mt++)
        #pragma unroll
        for (int h = 0; h < 2; h++) {
            const int j = mbase + mt * 16 + h * 8 + g;
            #pragma unroll
            for (int nt = 0; nt < 8; nt++) {
                const int l = lbase + nt * 4 + tg;
                dst[j * FNv + l] = outacc[mt][h][nt];
            }
        }
}

// ------------------------------ reduce kernel ------------------------------
__global__ void __launch_bounds__(256)
reduce_kernel(float* __restrict__ out) {
    const int f4 = blockIdx.x * 256 + threadIdx.x;   // 0..16383 float4 groups
    const int b = f4 >> 11;
    const int r = f4 & 2047;
    const float4* P = (const float4*)g_part;
    float4 s = make_float4(0.f, 0.f, 0.f, 0.f);
    #pragma unroll
    for (int c = 0; c < CHUNKS; c++) {
        const float4 v = P[((size_t)(b * CHUNKS + c)) * 2048 + r];
        s.x += v.x; s.y += v.y; s.z += v.z; s.w += v.w;
    }
    ((float4*)out)[b * 2048 + r] = s;
}

// ------------------------------ launch ------------------------------
extern "C" void kernel_launch(void* const* d_in, const int* in_sizes, int n_in,
                              void* d_out, int out_size) {
    const float* H    = (const float*)d_in[0];
    const float* A    = (const float*)d_in[1];
    const float* E    = (const float*)d_in[2];
    const float* Watt = (const float*)d_in[3];
    const float* Wnei = (const float*)d_in[4];
    const float* bAtt = (const float*)d_in[5];
    const float* bNei = (const float*)d_in[6];
    float* out = (float*)d_out;

    cudaFuncSetAttribute(main_kernel, cudaFuncAttributeMaxDynamicSharedMemorySize, SMEM_DYN);

    prep_kernel<<<136, 256>>>(H, Watt, Wnei);
    main_kernel<<<Bv * CHUNKS, 256, SMEM_DYN>>>(A, E, bAtt, bNei);
    reduce_kernel<<<64, 256>>>(out);
}